// round 2
// baseline (speedup 1.0000x reference)
#include <cuda_runtime.h>
#include <cuda_bf16.h>
#include <cstdint>

#define BB 64
#define SS 2048
#define DD 1024
#define SPLITS 16
#define S_PER (SS / SPLITS)   // 128

// Scratch (allocation-free rule: __device__ globals)
__device__ float g_weights[BB * SS];               // 512 KB
__device__ float g_partial[SPLITS * BB * DD];      // 4 MB

// ---------------------------------------------------------------------------
// Kernel 1: per-(b,s) weight = cnt>0 ? (mask ? 1/cnt : 0) : 1/S
// ---------------------------------------------------------------------------
__global__ void weights_kernel(const int* __restrict__ mask) {
    const int b   = blockIdx.x;
    const int tid = threadIdx.x;   // 256 threads

    int sum = 0;
    for (int s = tid; s < SS; s += 256)
        sum += mask[b * SS + s];

    // warp reduce
    #pragma unroll
    for (int o = 16; o > 0; o >>= 1)
        sum += __shfl_xor_sync(0xFFFFFFFFu, sum, o);

    __shared__ int ws[8];
    if ((tid & 31) == 0) ws[tid >> 5] = sum;
    __syncthreads();

    int cnt = 0;
    #pragma unroll
    for (int i = 0; i < 8; i++) cnt += ws[i];

    const float inv = (cnt > 0) ? (1.0f / (float)cnt) : (1.0f / (float)SS);
    for (int s = tid; s < SS; s += 256) {
        float w;
        if (cnt > 0) w = mask[b * SS + s] ? inv : 0.0f;
        else         w = inv;
        g_weights[b * SS + s] = w;
    }
}

// ---------------------------------------------------------------------------
// Kernel 2: weighted reduction over an S-split. Skips zero-weight rows via
// deterministic ballot compaction (saves ~50% HBM traffic on random masks).
// grid = (SPLITS, BB), block = 256. Each thread owns one float4 of D.
// ---------------------------------------------------------------------------
__global__ void __launch_bounds__(256)
pool_kernel(const float* __restrict__ hidden) {
    const int b     = blockIdx.y;
    const int split = blockIdx.x;
    const int s0    = split * S_PER;
    const int tid   = threadIdx.x;

    __shared__ float s_w[S_PER];
    __shared__ short s_idx[S_PER];
    __shared__ int   s_warpcnt[4];
    __shared__ int   s_n;

    // Load weights for this split, find nonzeros (deterministic compaction).
    float    myw  = 0.0f;
    unsigned ball = 0;
    if (tid < S_PER) {
        myw  = g_weights[b * SS + s0 + tid];
        ball = __ballot_sync(0xFFFFFFFFu, myw != 0.0f);
        if ((tid & 31) == 0) s_warpcnt[tid >> 5] = __popc(ball);
    }
    __syncthreads();

    if (tid < S_PER) {
        const int warp = tid >> 5, lane = tid & 31;
        if (myw != 0.0f) {
            int base = 0;
            #pragma unroll
            for (int i = 0; i < 4; i++) if (i < warp) base += s_warpcnt[i];
            const int pos = base + __popc(ball & ((1u << lane) - 1u));
            s_idx[pos] = (short)tid;
            s_w[pos]   = myw;
        }
        if (tid == 0)
            s_n = s_warpcnt[0] + s_warpcnt[1] + s_warpcnt[2] + s_warpcnt[3];
    }
    __syncthreads();

    const int n = s_n;
    // Base pointer: row s0 of batch b, this thread's float4 column.
    const float* rowbase = hidden + (size_t)b * SS * DD + (size_t)s0 * DD + (size_t)tid * 4;

    float ax = 0.0f, ay = 0.0f, az = 0.0f, aw = 0.0f;

    int i = 0;
    for (; i + 4 <= n; i += 4) {
        const int   r0 = s_idx[i + 0], r1 = s_idx[i + 1];
        const int   r2 = s_idx[i + 2], r3 = s_idx[i + 3];
        const float w0 = s_w[i + 0],   w1 = s_w[i + 1];
        const float w2 = s_w[i + 2],   w3 = s_w[i + 3];
        // 4 independent 16B loads in flight (MLP=4)
        const float4 v0 = *(const float4*)(rowbase + (size_t)r0 * DD);
        const float4 v1 = *(const float4*)(rowbase + (size_t)r1 * DD);
        const float4 v2 = *(const float4*)(rowbase + (size_t)r2 * DD);
        const float4 v3 = *(const float4*)(rowbase + (size_t)r3 * DD);
        ax = fmaf(w0, v0.x, ax); ay = fmaf(w0, v0.y, ay);
        az = fmaf(w0, v0.z, az); aw = fmaf(w0, v0.w, aw);
        ax = fmaf(w1, v1.x, ax); ay = fmaf(w1, v1.y, ay);
        az = fmaf(w1, v1.z, az); aw = fmaf(w1, v1.w, aw);
        ax = fmaf(w2, v2.x, ax); ay = fmaf(w2, v2.y, ay);
        az = fmaf(w2, v2.z, az); aw = fmaf(w2, v2.w, aw);
        ax = fmaf(w3, v3.x, ax); ay = fmaf(w3, v3.y, ay);
        az = fmaf(w3, v3.z, az); aw = fmaf(w3, v3.w, aw);
    }
    for (; i < n; i++) {
        const int   r = s_idx[i];
        const float w = s_w[i];
        const float4 v = *(const float4*)(rowbase + (size_t)r * DD);
        ax = fmaf(w, v.x, ax); ay = fmaf(w, v.y, ay);
        az = fmaf(w, v.z, az); aw = fmaf(w, v.w, aw);
    }

    float4 out;
    out.x = ax; out.y = ay; out.z = az; out.w = aw;
    ((float4*)g_partial)[(size_t)(split * BB + b) * (DD / 4) + tid] = out;
}

// ---------------------------------------------------------------------------
// Kernel 3: deterministic combine of SPLITS partials -> d_out.
// grid = 64, block = 256; one float4 of (B*D) per thread.
// ---------------------------------------------------------------------------
__global__ void combine_kernel(float* __restrict__ out) {
    const int idx = blockIdx.x * 256 + threadIdx.x;   // over B*D/4 = 16384
    const int b = idx / (DD / 4);
    const int c = idx % (DD / 4);

    float ax = 0.0f, ay = 0.0f, az = 0.0f, aw = 0.0f;
    #pragma unroll
    for (int sp = 0; sp < SPLITS; sp++) {
        const float4 v = ((const float4*)g_partial)[(size_t)(sp * BB + b) * (DD / 4) + c];
        ax += v.x; ay += v.y; az += v.z; aw += v.w;
    }
    float4 o;
    o.x = ax; o.y = ay; o.z = az; o.w = aw;
    ((float4*)out)[idx] = o;
}

// ---------------------------------------------------------------------------
extern "C" void kernel_launch(void* const* d_in, const int* in_sizes, int n_in,
                              void* d_out, int out_size) {
    const float* hidden = (const float*)d_in[0];
    const int*   mask   = (const int*)d_in[1];
    float*       out    = (float*)d_out;

    weights_kernel<<<BB, 256>>>(mask);
    dim3 grid(SPLITS, BB);
    pool_kernel<<<grid, 256>>>(hidden);
    combine_kernel<<<(BB * DD / 4) / 256, 256>>>(out);
}